// round 3
// baseline (speedup 1.0000x reference)
#include <cuda_runtime.h>
#include <math.h>

// Problem constants
#define DIMC   64
#define MULTI  4
#define NPIX   (8*256*256)        // 524288 pixels
#define PT     64                 // pixels per tile
#define NTILES (NPIX/PT)          // 8192
#define NTHREADS 512
#define NBLOCKS  148              // persistent, 1 block/SM

// smem layout (floats):
//   wgT[4][64][64]   : 16384 floats (wg transposed to [m][i][o], o contiguous)
//   ys [4][64][68]   : 17408 floats (y tile [m][i][p], p padded 64->68: stride
//                      68 == 4 mod 32 -> conflict-free 128-bit STS phases)
#define WG_FLOATS 16384
#define YP        68
#define YS_FLOATS (4*64*YP)
#define SMEM_BYTES ((WG_FLOATS + YS_FLOATS)*4)

typedef unsigned long long ull;

__device__ __forceinline__ float gelu_exact(float v) {
    // exact erf-based GELU, matches jax.nn.gelu(approximate=False)
    return 0.5f * v * (1.0f + erff(v * 0.70710678118654752f));
}

// packed fp32x2 FMA: d = a*b + d  (issue-slot saver; lane rate unchanged)
__device__ __forceinline__ void fma2(ull& d, ull a, ull b) {
    asm("fma.rn.f32x2 %0, %1, %2, %0;" : "+l"(d) : "l"(a), "l"(b));
}
__device__ __forceinline__ ull pack2(float v) {
    ull r;
    unsigned int u = __float_as_uint(v);
    asm("mov.b64 %0, {%1, %1};" : "=l"(r) : "r"(u));
    return r;
}
__device__ __forceinline__ float2 unpack2(ull v) {
    unsigned int lo, hi;
    asm("mov.b64 {%0, %1}, %2;" : "=r"(lo), "=r"(hi) : "l"(v));
    return make_float2(__uint_as_float(lo), __uint_as_float(hi));
}

__global__ void __launch_bounds__(NTHREADS, 1)
mpmlp_kernel(const float* __restrict__ x,
             const float* __restrict__ w1,
             const float* __restrict__ wg,
             const float* __restrict__ w2,
             float* __restrict__ out)
{
    extern __shared__ float sm[];
    float* wgT = sm;                 // [m][i][o]
    float* ys  = sm + WG_FLOATS;     // [m][i][p(68)]

    const int tid = threadIdx.x;

    // ---- one-time: load wg with transpose (m,o,i) -> (m,i,o) ----
    for (int idx = tid; idx < WG_FLOATS; idx += NTHREADS) {
        int m = idx >> 12;
        int o = (idx >> 6) & 63;
        int i = idx & 63;
        wgT[(m*64 + i)*64 + o] = wg[idx];
    }

    // ---- GEMM-side thread mapping ----
    // 512 threads = 16 warps. warp w covers pixels p0 = 4w .. 4w+3.
    // lane og: colA = 4*og in [0,128) -> mA = og>>4, oA = 4*(og&15); mB = mA+2.
    const int og = tid & 31;
    const int wrp = tid >> 5;          // 0..15
    const int p0 = wrp * 4;            // 4-pixel micro tile
    const int mA = og >> 4;            // 0 or 1
    const int oA = (og & 15) * 4;
    const int mB = mA + 2;

    // ---- producer-side thread mapping ----
    const int pi = tid & 63;           // channel i owned by this thread
    const int pq = tid >> 6;           // 0..7 -> pixels 8*pq .. 8*pq+7

    // preload small weights into registers
    const float4 w1v = *reinterpret_cast<const float4*>(w1 + pi*4); // w1[pi][0..3]
    float w2A[4], w2B[4];
#pragma unroll
    for (int t = 0; t < 4; t++) {
        w2A[t] = w2[(oA + t)*4 + mA];
        w2B[t] = w2[(oA + t)*4 + mB];
    }

    __syncthreads();

    // ---- prefetch first tile's x slice into registers ----
    int tile = blockIdx.x;
    float xv[8];
    {
        const long base = (long)tile * PT * DIMC;
#pragma unroll
        for (int t = 0; t < 8; t++)
            xv[t] = x[base + (long)(pq*8 + t)*DIMC + pi];
    }

    for (; tile < NTILES; tile += gridDim.x) {
        const long base = (long)tile * PT * DIMC;

        // ================= producer: y = gelu(xv * w1) into smem =================
        {
            const float w1a[4] = {w1v.x, w1v.y, w1v.z, w1v.w};
#pragma unroll
            for (int m = 0; m < 4; m++) {
#pragma unroll
                for (int half = 0; half < 2; half++) {
                    float4 yv;
                    yv.x = gelu_exact(xv[half*4+0]*w1a[m]);
                    yv.y = gelu_exact(xv[half*4+1]*w1a[m]);
                    yv.z = gelu_exact(xv[half*4+2]*w1a[m]);
                    yv.w = gelu_exact(xv[half*4+3]*w1a[m]);
                    *reinterpret_cast<float4*>(&ys[(m*64 + pi)*YP + pq*8 + half*4]) = yv;
                }
            }
        }
        __syncthreads();

        // ---- prefetch next tile's x (overlaps with GEMM below) ----
        {
            const int nt = tile + gridDim.x;
            const long nbase = (long)(nt < NTILES ? nt : tile) * PT * DIMC;
#pragma unroll
            for (int t = 0; t < 8; t++)
                xv[t] = x[nbase + (long)(pq*8 + t)*DIMC + pi];
        }

        // ================= middle GEMM: z_pre = Y @ WgT =================
        // acc[pp][t]: packed pixel pair (p0+2pp, p0+2pp+1), column oA+t.
        ull accA2[2][4];
        ull accB2[2][4];
#pragma unroll
        for (int p = 0; p < 2; p++)
#pragma unroll
            for (int t = 0; t < 4; t++) { accA2[p][t] = 0ull; accB2[p][t] = 0ull; }

        const float* wgA = &wgT[(mA*64)*64 + oA];
        const float* wgB = &wgT[(mB*64)*64 + oA];
        const float* ysA = &ys[(mA*64)*YP + p0];
        const float* ysB = &ys[(mB*64)*YP + p0];

#pragma unroll 16
        for (int k = 0; k < 64; k++) {
            const float4 wa = *reinterpret_cast<const float4*>(wgA + k*64);
            const float4 wb = *reinterpret_cast<const float4*>(wgB + k*64);
            // y loads: broadcast within each half-warp (same p0 per warp)
            const ulonglong2 ya = *reinterpret_cast<const ulonglong2*>(ysA + k*YP);
            const ulonglong2 yb = *reinterpret_cast<const ulonglong2*>(ysB + k*YP);

            const ull yav[2] = {ya.x, ya.y};
            const ull ybv[2] = {yb.x, yb.y};
            const ull wa2[4] = {pack2(wa.x), pack2(wa.y), pack2(wa.z), pack2(wa.w)};
            const ull wb2[4] = {pack2(wb.x), pack2(wb.y), pack2(wb.z), pack2(wb.w)};

#pragma unroll
            for (int p = 0; p < 2; p++) {
#pragma unroll
                for (int t = 0; t < 4; t++) {
                    fma2(accA2[p][t], yav[p], wa2[t]);
                    fma2(accB2[p][t], ybv[p], wb2[t]);
                }
            }
        }
        __syncthreads();   // GEMM reads of ys done before next tile's producer

        // ================= epilogue: gelu(z), contract over m, store =================
        // lane og holds m = {mA, mB}; partner lane og^16 holds the complementary
        // m-pair for the SAME output channels oA..oA+3.
#pragma unroll
        for (int pp = 0; pp < 2; pp++) {
            float2 aA[4], aB[4];
#pragma unroll
            for (int t = 0; t < 4; t++) {
                aA[t] = unpack2(accA2[pp][t]);
                aB[t] = unpack2(accB2[pp][t]);
            }
#pragma unroll
            for (int h = 0; h < 2; h++) {
                const int p = 2*pp + h;
                float part[4];
#pragma unroll
                for (int t = 0; t < 4; t++) {
                    const float va = h ? aA[t].y : aA[t].x;
                    const float vb = h ? aB[t].y : aB[t].x;
                    part[t] = gelu_exact(va) * w2A[t] + gelu_exact(vb) * w2B[t];
                }
                float other[4];
#pragma unroll
                for (int t = 0; t < 4; t++)
                    other[t] = __shfl_xor_sync(0xffffffffu, part[t], 16);

                if (og < 16) {
                    float4 o4;
                    o4.x = part[0] + other[0];
                    o4.y = part[1] + other[1];
                    o4.z = part[2] + other[2];
                    o4.w = part[3] + other[3];
                    *reinterpret_cast<float4*>(&out[base + (long)(p0 + p)*DIMC + oA]) = o4;
                }
            }
        }
    }
}

extern "C" void kernel_launch(void* const* d_in, const int* in_sizes, int n_in,
                              void* d_out, int out_size)
{
    const float* x  = (const float*)d_in[0];
    const float* w1 = (const float*)d_in[1];
    const float* wg = (const float*)d_in[2];
    const float* w2 = (const float*)d_in[3];
    float* out = (float*)d_out;

    cudaFuncSetAttribute(mpmlp_kernel,
                         cudaFuncAttributeMaxDynamicSharedMemorySize, SMEM_BYTES);
    mpmlp_kernel<<<NBLOCKS, NTHREADS, SMEM_BYTES>>>(x, w1, wg, w2, out);
}